// round 15
// baseline (speedup 1.0000x reference)
#include <cuda_runtime.h>
#include <cuda_fp16.h>
#include <cstdint>

#define B_    4096
#define H_    512
#define TOBS  30
#define TPRED 60

// ------------------ device scratch (static, no runtime alloc) ------------------
__device__ float g_h0[2][B_ * H_];
__device__ float g_h1[2][B_ * H_];
__device__ float g_hd[2][B_ * H_];
__device__ __half g_h1h[2][B_ * H_];
__device__ __half g_hdh[2][B_ * H_];
__device__ __half g_h0seq[TOBS + 1][B_ * H_];       // layer0 fp16 images, [0]=zeros
__device__ __half g_gi[(size_t)TOBS * B_ * 1536];   // batched layer1 input GEMM results
__device__ float g_decin0[B_ * 2];
__device__ float g_pred[3][B_ * 2];                 // decoder pred partials (3-phase)
// packed fp16 weights for LDS.128 reads (see prep)
__device__ uint32_t g_Wp[4][393216];   // {W_hh0, W_ih1, W_hh1, W_hhd}
// combined bias table per layer: [j][4] = {bih_r+bhh_r, bih_z+bhh_z, bih_n, bhh_n}
__device__ float g_b4[3][H_ * 4];

// smem: 5-stage pipeline of K=32 chunks, tile 128m x 64n.
// A stage: 128 rows x 40 halves (pitch 40, rows 80B = 5x16B aligned) = 10240B
// B stage: 24 blocks x 512B = 12288B
#define SMA_BYTES 10240
#define SMB_BYTES 12288
#define NSTAGE    5
#define SMB_OFF   (NSTAGE * SMA_BYTES)                 // 51200
#define SMEM_BYTES (NSTAGE * (SMA_BYTES + SMB_BYTES))  // 112640

// ------------------ helpers ------------------
__device__ __forceinline__ void mma16(float c[4], uint32_t a0, uint32_t a1, uint32_t a2,
                                      uint32_t a3, uint32_t b0, uint32_t b1) {
    asm volatile(
        "mma.sync.aligned.m16n8k16.row.col.f32.f16.f16.f32 "
        "{%0,%1,%2,%3},{%4,%5,%6,%7},{%8,%9},{%0,%1,%2,%3};"
        : "+f"(c[0]), "+f"(c[1]), "+f"(c[2]), "+f"(c[3])
        : "r"(a0), "r"(a1), "r"(a2), "r"(a3), "r"(b0), "r"(b1));
}
__device__ __forceinline__ void ldsm4(uint32_t a[4], uint32_t addr) {
    asm volatile("ldmatrix.sync.aligned.m8n8.x4.shared.b16 {%0,%1,%2,%3}, [%4];"
                 : "=r"(a[0]), "=r"(a[1]), "=r"(a[2]), "=r"(a[3]) : "r"(addr));
}
__device__ __forceinline__ void cpasync16(uint32_t dst, const void* src) {
    asm volatile("cp.async.cg.shared.global [%0], [%1], 16;" :: "r"(dst), "l"(src));
}
__device__ __forceinline__ float sigf(float v) { return 1.0f / (1.0f + __expf(-v)); }

// ------------------ prep: pack fp16 weights + combined biases ------------------
__global__ void prep_kernel(const float* __restrict__ Whh0, const float* __restrict__ Wih1,
                            const float* __restrict__ Whh1, const float* __restrict__ Whhd,
                            const float* __restrict__ bih0, const float* __restrict__ bhh0,
                            const float* __restrict__ bih1, const float* __restrict__ bhh1,
                            const float* __restrict__ bihd, const float* __restrict__ bhhd) {
    const int NW = 4 * 393216;
    const int total = NW + 3 * 2048;
    for (int idx = blockIdx.x * blockDim.x + threadIdx.x; idx < total;
         idx += gridDim.x * blockDim.x) {
        if (idx < NW) {
            int mat = idx / 393216, r = idx % 393216;
            int kb = r / 12288, r2 = r % 12288;
            int g = r2 / 4096, r3 = r2 % 4096;
            int jb2 = r3 / 128, r4 = r3 % 128;
            int lane = r4 >> 2, q = r4 & 3;
            int jb = jb2 * 2 + (q >> 1), v = q & 1;
            int row = g * 512 + jb * 8 + (lane >> 2);
            int k0 = kb * 16 + 2 * (lane & 3) + 8 * v;
            const float* Wsrc = (mat == 0) ? Whh0 : (mat == 1) ? Wih1 : (mat == 2) ? Whh1 : Whhd;
            __half2 hv = __floats2half2_rn(Wsrc[row * 512 + k0], Wsrc[row * 512 + k0 + 1]);
            g_Wp[mat][r] = *reinterpret_cast<uint32_t*>(&hv);
        } else {
            int r = idx - NW;
            int l = r / 2048, rem = r % 2048;
            int j = rem >> 2, s = rem & 3;
            const float* bi = (l == 0) ? bih0 : (l == 1) ? bih1 : bihd;
            const float* bh = (l == 0) ? bhh0 : (l == 1) ? bhh1 : bhhd;
            float v;
            if (s == 0)      v = bi[j] + bh[j];
            else if (s == 1) v = bi[512 + j] + bh[512 + j];
            else if (s == 2) v = bi[1024 + j];
            else             v = bh[1024 + j];
            g_b4[l][j * 4 + s] = v;
        }
    }
}

__global__ void init_kernel(const float* __restrict__ x) {
    int idx0 = blockIdx.x * blockDim.x + threadIdx.x;
    for (int i = idx0; i < B_ * H_; i += gridDim.x * blockDim.x) {
        g_h0[0][i] = 0.0f;  g_h1[0][i] = 0.0f;
        g_h0seq[0][i] = __float2half(0.0f);
        g_h1h[0][i] = __float2half(0.0f);
    }
    if (idx0 < B_ * 2) {
        int m = idx0 >> 1, o = idx0 & 1;
        g_decin0[idx0] = x[m * 120 + 116 + o];  // x[m][29][o]
    }
    if (idx0 < 3 * B_ * 2) {
        g_pred[idx0 / (B_ * 2)][idx0 % (B_ * 2)] = 0.0f;
    }
}

// ------------------ fused single-pass GRU step / batched gi GEMM ------------------
// Tile 128m x 64n, grid (32, 8) = 256 CTAs = ONE wave at 2 CTAs/SM.
// 8 warps: wm = w&3 (32m), wn = w>>2 in {0,1} (32n each), warp tile 32x32 per gate.
// MODE 0: encoder layer0. MODE 2: decoder (FC fused). MODE 3: layer1 gh-only.
// MODE 4: batched gi GEMM over blockIdx.z = t.
// 16 chunks of K=32, 5 smem stages, 4 in flight.
template <int MODE>
__global__ void __launch_bounds__(256, 2)
gru_core(int t, const float* __restrict__ x, const float* __restrict__ Wraw,
         const float* __restrict__ Wfc, const float* __restrict__ bfc,
         float* __restrict__ out) {
    extern __shared__ char smem[];
    uint32_t sb = (uint32_t)__cvta_generic_to_shared(smem);
    const int tid = threadIdx.x, lane = tid & 31, w = tid >> 5;
    const int wm = w & 3, wn = w >> 2;            // 4 M-warps x 2 N-warps (32n each)
    const int m0 = blockIdx.x * 128;
    const int y = blockIdx.y;                     // 8 n-slices of 64 cols
    const int n0 = y * 64;
    const int zt = (MODE == 4) ? blockIdx.z : t;

    const uint32_t* Wp;
    if constexpr (MODE == 0)      Wp = g_Wp[0];
    else if constexpr (MODE == 2) Wp = g_Wp[3];
    else if constexpr (MODE == 3) Wp = g_Wp[2];
    else                          Wp = g_Wp[1];

    // ---- pre-sync: weight prefetch for chunks 0..3 (independent of prev step) ----
    auto load_B = [&](int c) {
        const uint32_t bbase = sb + SMB_OFF + (c % NSTAGE) * SMB_BYTES;
#pragma unroll
        for (int i = 0; i < 3; ++i) {
            int u = tid + i * 256;                // 0..767 = 24 blocks x 32 uint4
            int blk = u >> 5, q = u & 31;
            int ks = blk / 12, r12 = blk % 12;
            int g = r12 >> 2, jl = r12 & 3;
            cpasync16(bbase + (uint32_t)(blk * 512 + q * 16),
                      Wp + ((((c * 2 + ks) * 3 + g) * 32 + (y * 4 + jl)) * 32 + q) * 4);
        }
        asm volatile("cp.async.commit_group;" ::: "memory");
    };
#pragma unroll
    for (int c = 0; c < 4; ++c) load_B(c);
    cudaTriggerProgrammaticLaunchCompletion();
    cudaGridDependencySynchronize();

    // ---- post-sync: everything touching the previous step's outputs ----
    const __half* Aimg;
    const float* b4p = nullptr;
    const float* hin = nullptr;
    float* hout = nullptr;
    __half* himg = nullptr;
    if constexpr (MODE == 0) {
        Aimg = g_h0seq[zt];
        hin = g_h0[zt & 1]; hout = g_h0[(zt + 1) & 1]; himg = g_h0seq[zt + 1];
        b4p = g_b4[0];
    } else if constexpr (MODE == 2) {
        Aimg = (zt == 0) ? g_h1h[0] : g_hdh[zt & 1];
        hin = (zt == 0) ? g_h1[0] : g_hd[zt & 1];
        hout = g_hd[(zt + 1) & 1]; himg = g_hdh[(zt + 1) & 1];
        b4p = g_b4[2];
    } else if constexpr (MODE == 3) {
        Aimg = g_h1h[zt & 1];
        hin = g_h1[zt & 1]; hout = g_h1[(zt + 1) & 1]; himg = g_h1h[(zt + 1) & 1];
        b4p = g_b4[1];
    } else {
        Aimg = g_h0seq[zt + 1];   // gi(t) = h0(t+1) @ Wih1^T
    }

    float bfc0 = 0.f, bfc1 = 0.f;
    if constexpr (MODE == 2) { bfc0 = bfc[0]; bfc1 = bfc[1]; }

    float acc[3][2][4][4];
#pragma unroll
    for (int s = 0; s < 3; ++s)
#pragma unroll
        for (int mf = 0; mf < 2; ++mf)
#pragma unroll
            for (int nf = 0; nf < 4; ++nf)
#pragma unroll
                for (int q = 0; q < 4; ++q) acc[s][mf][nf][q] = 0.0f;

    const int laneRow = (lane & 7) + ((lane >> 3) & 1) * 8;
    const int laneCol = (lane >> 4) * 8;
    const uint32_t aoff = (uint32_t)(((wm * 32 + laneRow) * 40 + laneCol) * 2);

    auto load_A = [&](int c) {
        const uint32_t abase = sb + (c % NSTAGE) * SMA_BYTES;
#pragma unroll
        for (int i = 0; i < 2; ++i) {
            int u = tid + i * 256;                // 0..511
            int row = u >> 2, c8 = (u & 3) << 3;
            cpasync16(abase + (uint32_t)((row * 40 + c8) * 2),
                      Aimg + (m0 + row) * 512 + c * 32 + c8);
        }
        asm volatile("cp.async.commit_group;" ::: "memory");
    };
    auto load_AB = [&](int c) {
        const int b = c % NSTAGE;
        const uint32_t abase = sb + b * SMA_BYTES;
        const uint32_t bbase = sb + SMB_OFF + b * SMB_BYTES;
#pragma unroll
        for (int i = 0; i < 2; ++i) {
            int u = tid + i * 256;
            int row = u >> 2, c8 = (u & 3) << 3;
            cpasync16(abase + (uint32_t)((row * 40 + c8) * 2),
                      Aimg + (m0 + row) * 512 + c * 32 + c8);
        }
#pragma unroll
        for (int i = 0; i < 3; ++i) {
            int u = tid + i * 256;
            int blk = u >> 5, q = u & 31;
            int ks = blk / 12, r12 = blk % 12;
            int g = r12 >> 2, jl = r12 & 3;
            cpasync16(bbase + (uint32_t)(blk * 512 + q * 16),
                      Wp + ((((c * 2 + ks) * 3 + g) * 32 + (y * 4 + jl)) * 32 + q) * 4);
        }
        asm volatile("cp.async.commit_group;" ::: "memory");
    };

    // prologue A loads for chunks 0..3. Group order: B0..B3, A0..A3, then AB4..AB15.
#pragma unroll
    for (int c = 0; c < 4; ++c) load_A(c);

    for (int cg = 0; cg < 16; ++cg) {
        if (cg <= 12)
            asm volatile("cp.async.wait_group 3;" ::: "memory");
        else if (cg == 13)
            asm volatile("cp.async.wait_group 2;" ::: "memory");
        else if (cg == 14)
            asm volatile("cp.async.wait_group 1;" ::: "memory");
        else
            asm volatile("cp.async.wait_group 0;" ::: "memory");
        __syncthreads();
        if (cg + 4 < 16) load_AB(cg + 4);
        const int b = cg % NSTAGE;
        const uint32_t abase = sb + b * SMA_BYTES;
        const uint4* sB = reinterpret_cast<const uint4*>(smem + SMB_OFF + b * SMB_BYTES);
#pragma unroll
        for (int ks = 0; ks < 2; ++ks) {   // 2 x k16 per 32-col chunk
            uint32_t a[2][4];
            ldsm4(a[0], abase + aoff + ks * 32);
            ldsm4(a[1], abase + aoff + 1280 + ks * 32);   // mf=1: +16 rows * 80B
#pragma unroll
            for (int g = 0; g < 3; ++g) {
#pragma unroll
                for (int nf2 = 0; nf2 < 2; ++nf2) {
                    const uint4 bv = sB[((ks * 3 + g) * 4 + wn * 2 + nf2) * 32 + lane];
                    mma16(acc[g][0][nf2 * 2], a[0][0], a[0][1], a[0][2], a[0][3], bv.x, bv.y);
                    mma16(acc[g][1][nf2 * 2], a[1][0], a[1][1], a[1][2], a[1][3], bv.x, bv.y);
                    mma16(acc[g][0][nf2 * 2 + 1], a[0][0], a[0][1], a[0][2], a[0][3], bv.z, bv.w);
                    mma16(acc[g][1][nf2 * 2 + 1], a[1][0], a[1][1], a[1][2], a[1][3], bv.z, bv.w);
                }
            }
        }
    }

    // ------------- epilogue -------------
    if constexpr (MODE == 4) {
#pragma unroll
        for (int mf = 0; mf < 2; ++mf) {
#pragma unroll
            for (int rr = 0; rr < 2; ++rr) {
                int m = m0 + wm * 32 + mf * 16 + rr * 8 + (lane >> 2);
                size_t base = ((size_t)zt * B_ + m) * 1536;
#pragma unroll
                for (int nf = 0; nf < 4; ++nf) {
                    int j = n0 + wn * 32 + nf * 8 + (lane & 3) * 2;
#pragma unroll
                    for (int g = 0; g < 3; ++g) {
                        __half2 hv = __floats2half2_rn(acc[g][mf][nf][rr * 2],
                                                       acc[g][mf][nf][rr * 2 + 1]);
                        *reinterpret_cast<__half2*>(&g_gi[base + g * 512 + j]) = hv;
                    }
                }
            }
        }
        return;
    }

#pragma unroll
    for (int mf = 0; mf < 2; ++mf) {
#pragma unroll
        for (int rr = 0; rr < 2; ++rr) {
            int m = m0 + wm * 32 + mf * 16 + rr * 8 + (lane >> 2);
            float4 xr = make_float4(0.f, 0.f, 0.f, 0.f);
            float2 x2 = make_float2(0.f, 0.f);
            if constexpr (MODE == 0) xr = *reinterpret_cast<const float4*>(&x[m * 120 + zt * 4]);
            if constexpr (MODE == 2) {
                if (zt == 0) {
                    x2 = *reinterpret_cast<const float2*>(&g_decin0[m * 2]);
                } else {
                    float2 p = *reinterpret_cast<const float2*>(&g_pred[(zt - 1) % 3][m * 2]);
                    x2 = make_float2(p.x + bfc0, p.y + bfc1);
                    if (y == 0 && wn == 0 && (lane & 3) == 0) {
                        out[m * 120 + (zt - 1) * 2] = x2.x;
                        out[m * 120 + (zt - 1) * 2 + 1] = x2.y;
                    }
                }
            }
            size_t gibase = 0;
            if constexpr (MODE == 3) gibase = ((size_t)zt * B_ + m) * 1536;
            float pp0 = 0.f, pp1 = 0.f;
#pragma unroll
            for (int nf = 0; nf < 4; ++nf) {
                int j = n0 + wn * 32 + nf * 8 + (lane & 3) * 2;
                float2 ho = *reinterpret_cast<const float2*>(&hin[m * 512 + j]);
                float2 gr2 = make_float2(0.f, 0.f), gz2 = gr2, gn2 = gr2;
                if constexpr (MODE == 3) {
                    gr2 = __half22float2(*reinterpret_cast<const __half2*>(&g_gi[gibase + j]));
                    gz2 = __half22float2(
                        *reinterpret_cast<const __half2*>(&g_gi[gibase + 512 + j]));
                    gn2 = __half22float2(
                        *reinterpret_cast<const __half2*>(&g_gi[gibase + 1024 + j]));
                }
                float hnew[2];
#pragma unroll
                for (int cc = 0; cc < 2; ++cc) {
                    int jj = j + cc;
                    float4 bb = *reinterpret_cast<const float4*>(&b4p[jj * 4]);
                    int q = rr * 2 + cc;
                    float gir = 0.f, giz = 0.f, gin = 0.f;
                    if constexpr (MODE == 0) {
                        float4 wr = *reinterpret_cast<const float4*>(&Wraw[jj * 4]);
                        float4 wz = *reinterpret_cast<const float4*>(&Wraw[(jj + 512) * 4]);
                        float4 wn4 = *reinterpret_cast<const float4*>(&Wraw[(jj + 1024) * 4]);
                        gir = xr.x * wr.x + xr.y * wr.y + xr.z * wr.z + xr.w * wr.w;
                        giz = xr.x * wz.x + xr.y * wz.y + xr.z * wz.z + xr.w * wz.w;
                        gin = xr.x * wn4.x + xr.y * wn4.y + xr.z * wn4.z + xr.w * wn4.w;
                    } else if constexpr (MODE == 2) {
                        float2 wr = *reinterpret_cast<const float2*>(&Wraw[jj * 2]);
                        float2 wz = *reinterpret_cast<const float2*>(&Wraw[(jj + 512) * 2]);
                        float2 wn2 = *reinterpret_cast<const float2*>(&Wraw[(jj + 1024) * 2]);
                        gir = x2.x * wr.x + x2.y * wr.y;
                        giz = x2.x * wz.x + x2.y * wz.y;
                        gin = x2.x * wn2.x + x2.y * wn2.y;
                    } else {
                        gir = cc ? gr2.y : gr2.x;
                        giz = cc ? gz2.y : gz2.x;
                        gin = cc ? gn2.y : gn2.x;
                    }
                    float rg = sigf(acc[0][mf][nf][q] + gir + bb.x);
                    float zg = sigf(acc[1][mf][nf][q] + giz + bb.y);
                    float ng = tanhf(gin + bb.z + rg * (acc[2][mf][nf][q] + bb.w));
                    float hprev = cc ? ho.y : ho.x;
                    hnew[cc] = (1.0f - zg) * ng + zg * hprev;
                    if constexpr (MODE == 2) {
                        pp0 += hnew[cc] * Wfc[jj];
                        pp1 += hnew[cc] * Wfc[512 + jj];
                    }
                }
                *reinterpret_cast<float2*>(&hout[m * 512 + j]) = make_float2(hnew[0], hnew[1]);
                __half2 hh = __floats2half2_rn(hnew[0], hnew[1]);
                *reinterpret_cast<__half2*>(&himg[m * 512 + j]) = hh;
            }
            if constexpr (MODE == 2) {
                atomicAdd(&g_pred[zt % 3][m * 2], pp0);
                atomicAdd(&g_pred[zt % 3][m * 2 + 1], pp1);
            }
        }
    }

    if constexpr (MODE == 2) {   // zero the phase step t+1 will accumulate into
        if (y == 1) {
            g_pred[(zt + 1) % 3][blockIdx.x * 256 + tid] = 0.0f;
        }
    }
}

// final pred -> out[TPRED-1]
__global__ void fc_final(const float* __restrict__ bfc, float* __restrict__ out) {
    int i = blockIdx.x * blockDim.x + threadIdx.x;
    if (i < B_) {
        float2 p = *reinterpret_cast<const float2*>(&g_pred[(TPRED - 1) % 3][i * 2]);
        out[i * 120 + (TPRED - 1) * 2] = p.x + bfc[0];
        out[i * 120 + (TPRED - 1) * 2 + 1] = p.y + bfc[1];
    }
}

// ------------------ launch ------------------
template <int MODE>
static void launch_step(dim3 grid, bool pdl, int t, const float* x, const float* Wraw,
                        const float* Wfc, const float* bfc, float* out) {
    cudaLaunchConfig_t cfg = {};
    cfg.gridDim = grid;
    cfg.blockDim = dim3(256, 1, 1);
    cfg.dynamicSmemBytes = SMEM_BYTES;
    cfg.stream = 0;
    cudaLaunchAttribute attr[1];
    attr[0].id = cudaLaunchAttributeProgrammaticStreamSerialization;
    attr[0].val.programmaticStreamSerializationAllowed = 1;
    if (pdl) { cfg.attrs = attr; cfg.numAttrs = 1; }
    cudaLaunchKernelEx(&cfg, gru_core<MODE>, t, x, Wraw, Wfc, bfc, out);
}

extern "C" void kernel_launch(void* const* d_in, const int* in_sizes, int n_in,
                              void* d_out, int out_size) {
    (void)in_sizes; (void)n_in; (void)out_size;
    const float* x    = (const float*)d_in[0];
    const float* Wih0 = (const float*)d_in[1];
    const float* Whh0 = (const float*)d_in[2];
    const float* bih0 = (const float*)d_in[3];
    const float* bhh0 = (const float*)d_in[4];
    const float* Wih1 = (const float*)d_in[5];
    const float* Whh1 = (const float*)d_in[6];
    const float* bih1 = (const float*)d_in[7];
    const float* bhh1 = (const float*)d_in[8];
    const float* Wihd = (const float*)d_in[9];
    const float* Whhd = (const float*)d_in[10];
    const float* bihd = (const float*)d_in[11];
    const float* bhhd = (const float*)d_in[12];
    const float* Wfc  = (const float*)d_in[13];
    const float* bfc  = (const float*)d_in[14];
    float* out = (float*)d_out;

    cudaFuncSetAttribute(gru_core<0>, cudaFuncAttributeMaxDynamicSharedMemorySize, SMEM_BYTES);
    cudaFuncSetAttribute(gru_core<2>, cudaFuncAttributeMaxDynamicSharedMemorySize, SMEM_BYTES);
    cudaFuncSetAttribute(gru_core<3>, cudaFuncAttributeMaxDynamicSharedMemorySize, SMEM_BYTES);
    cudaFuncSetAttribute(gru_core<4>, cudaFuncAttributeMaxDynamicSharedMemorySize, SMEM_BYTES);

    prep_kernel<<<1024, 256>>>(Whh0, Wih1, Whh1, Whhd,
                               bih0, bhh0, bih1, bhh1, bihd, bhhd);
    init_kernel<<<2048, 256>>>(x);

    dim3 grid(32, 8);
    // encoder layer 0 (sequential). t=0 non-PDL: its weight prefetch reads g_Wp from prep.
    for (int t = 0; t < TOBS; ++t) {
        launch_step<0>(grid, t > 0, t, x, Wih0, nullptr, nullptr, nullptr);
    }
    // batched layer-1 input GEMM for all timesteps (fully parallel)
    launch_step<4>(dim3(32, 8, TOBS), true, 0, x, nullptr, nullptr, nullptr, nullptr);
    // encoder layer 1 (sequential, gh-only)
    for (int t = 0; t < TOBS; ++t) {
        launch_step<3>(grid, true, t, x, nullptr, nullptr, nullptr, nullptr);
    }
    // decoder (FC fused)
    for (int td = 0; td < TPRED; ++td) {
        launch_step<2>(grid, true, td, x, Wihd, Wfc, bfc, out);
    }
    fc_final<<<16, 256>>>(bfc, out);
}

// round 16
// speedup vs baseline: 1.1616x; 1.1616x over previous
#include <cuda_runtime.h>
#include <cuda_fp16.h>
#include <cstdint>

#define B_    4096
#define H_    512
#define TOBS  30
#define TPRED 60

// ------------------ device scratch (static, no runtime alloc) ------------------
// Recurrent state lives ONLY as fp16 images (also the MMA A operand).
__device__ __half g_h1h[2][B_ * H_];
__device__ __half g_hdh[2][B_ * H_];
__device__ __half g_h0seq[TOBS + 1][B_ * H_];       // layer0 fp16 images, [0]=zeros
__device__ __half g_gi[(size_t)TOBS * B_ * 1536];   // batched layer1 input GEMM results
__device__ float g_decin0[B_ * 2];
__device__ float g_pred[3][B_ * 2];                 // decoder pred partials (3-phase)
// packed fp16 weights for LDS.128 reads (see prep)
__device__ uint32_t g_Wp[4][393216];   // {W_hh0, W_ih1, W_hh1, W_hhd}
// combined bias table per layer: [j][4] = {bih_r+bhh_r, bih_z+bhh_z, bih_n, bhh_n}
__device__ float g_b4[3][H_ * 4];

// smem: 6-stage pipeline of K=32 chunks.
// A stage: 128 rows x 40 halves (pitch 40, rows 80B = 5x16B aligned) = 10240B
// B stage: 12 blocks x 512B = 6144B
#define SMA_BYTES 10240
#define SMB_BYTES 6144
#define NSTAGE    6
#define SMB_OFF   (NSTAGE * SMA_BYTES)              // 61440
#define SMEM_BYTES (NSTAGE * (SMA_BYTES + SMB_BYTES))  // 98304

// ------------------ helpers ------------------
__device__ __forceinline__ void mma16(float c[4], uint32_t a0, uint32_t a1, uint32_t a2,
                                      uint32_t a3, uint32_t b0, uint32_t b1) {
    asm volatile(
        "mma.sync.aligned.m16n8k16.row.col.f32.f16.f16.f32 "
        "{%0,%1,%2,%3},{%4,%5,%6,%7},{%8,%9},{%0,%1,%2,%3};"
        : "+f"(c[0]), "+f"(c[1]), "+f"(c[2]), "+f"(c[3])
        : "r"(a0), "r"(a1), "r"(a2), "r"(a3), "r"(b0), "r"(b1));
}
__device__ __forceinline__ void ldsm4(uint32_t a[4], uint32_t addr) {
    asm volatile("ldmatrix.sync.aligned.m8n8.x4.shared.b16 {%0,%1,%2,%3}, [%4];"
                 : "=r"(a[0]), "=r"(a[1]), "=r"(a[2]), "=r"(a[3]) : "r"(addr));
}
__device__ __forceinline__ void cpasync16(uint32_t dst, const void* src) {
    asm volatile("cp.async.cg.shared.global [%0], [%1], 16;" :: "r"(dst), "l"(src));
}
__device__ __forceinline__ float sigf(float v) { return 1.0f / (1.0f + __expf(-v)); }

// ------------------ prep: pack fp16 weights + combined biases ------------------
__global__ void prep_kernel(const float* __restrict__ Whh0, const float* __restrict__ Wih1,
                            const float* __restrict__ Whh1, const float* __restrict__ Whhd,
                            const float* __restrict__ bih0, const float* __restrict__ bhh0,
                            const float* __restrict__ bih1, const float* __restrict__ bhh1,
                            const float* __restrict__ bihd, const float* __restrict__ bhhd) {
    const int NW = 4 * 393216;
    const int total = NW + 3 * 2048;
    for (int idx = blockIdx.x * blockDim.x + threadIdx.x; idx < total;
         idx += gridDim.x * blockDim.x) {
        if (idx < NW) {
            int mat = idx / 393216, r = idx % 393216;
            int kb = r / 12288, r2 = r % 12288;
            int g = r2 / 4096, r3 = r2 % 4096;
            int jb2 = r3 / 128, r4 = r3 % 128;
            int lane = r4 >> 2, q = r4 & 3;
            int jb = jb2 * 2 + (q >> 1), v = q & 1;
            int row = g * 512 + jb * 8 + (lane >> 2);
            int k0 = kb * 16 + 2 * (lane & 3) + 8 * v;
            const float* Wsrc = (mat == 0) ? Whh0 : (mat == 1) ? Wih1 : (mat == 2) ? Whh1 : Whhd;
            __half2 hv = __floats2half2_rn(Wsrc[row * 512 + k0], Wsrc[row * 512 + k0 + 1]);
            g_Wp[mat][r] = *reinterpret_cast<uint32_t*>(&hv);
        } else {
            int r = idx - NW;
            int l = r / 2048, rem = r % 2048;
            int j = rem >> 2, s = rem & 3;
            const float* bi = (l == 0) ? bih0 : (l == 1) ? bih1 : bihd;
            const float* bh = (l == 0) ? bhh0 : (l == 1) ? bhh1 : bhhd;
            float v;
            if (s == 0)      v = bi[j] + bh[j];
            else if (s == 1) v = bi[512 + j] + bh[512 + j];
            else if (s == 2) v = bi[1024 + j];
            else             v = bh[1024 + j];
            g_b4[l][j * 4 + s] = v;
        }
    }
}

__global__ void init_kernel(const float* __restrict__ x) {
    int idx0 = blockIdx.x * blockDim.x + threadIdx.x;
    for (int i = idx0; i < B_ * H_; i += gridDim.x * blockDim.x) {
        g_h0seq[0][i] = __float2half(0.0f);
        g_h1h[0][i] = __float2half(0.0f);
    }
    if (idx0 < B_ * 2) {
        int m = idx0 >> 1, o = idx0 & 1;
        g_decin0[idx0] = x[m * 120 + 116 + o];  // x[m][29][o]
    }
    if (idx0 < 3 * B_ * 2) {
        g_pred[idx0 / (B_ * 2)][idx0 % (B_ * 2)] = 0.0f;
    }
}

// ------------------ fused single-pass GRU step / batched gi GEMM ------------------
// MODE 0: encoder layer0 (x K=4 scalar ih, tensor hh; himg -> g_h0seq[t+1])
// MODE 2: decoder (pred K=2 scalar ih, tensor hh, FC fused via 3-phase g_pred)
// MODE 3: layer1 gh-only step (gi read from g_gi)
// MODE 4: batched gi GEMM over blockIdx.z = t (pure GEMM, fp16 out)
// 16 chunks of K=32, 6 smem stages, 5 chunks in flight (wait_group 4).
// hprev is read from the SAME fp16 image that feeds the MMA (no fp32 h state).
template <int MODE>
__global__ void __launch_bounds__(256, 2)
gru_core(int t, const float* __restrict__ x, const float* __restrict__ Wraw,
         const float* __restrict__ Wfc, const float* __restrict__ bfc,
         float* __restrict__ out) {
    extern __shared__ char smem[];
    uint32_t sb = (uint32_t)__cvta_generic_to_shared(smem);
    const int tid = threadIdx.x, lane = tid & 31, w = tid >> 5;
    const int wm = w & 3, wn = w >> 2;            // 4 M-warps x 2 N-warps
    const int m0 = blockIdx.x * 128;
    const int y = blockIdx.y;
    const int n0 = y * 32;
    const int zt = (MODE == 4) ? blockIdx.z : t;

    const uint32_t* Wp;
    if constexpr (MODE == 0)      Wp = g_Wp[0];
    else if constexpr (MODE == 2) Wp = g_Wp[3];
    else if constexpr (MODE == 3) Wp = g_Wp[2];
    else                          Wp = g_Wp[1];

    // ---- pre-sync: weight prefetch for chunks 0..4 (independent of prev step) ----
    auto load_B = [&](int c) {
        const uint32_t bbase = sb + SMB_OFF + (c % NSTAGE) * SMB_BYTES;
#pragma unroll
        for (int i = 0; i < 2; ++i) {
            int u = tid + i * 256;                // 0..511, need 0..383
            if (u < 384) {
                int blk = u >> 5, q = u & 31;     // blk = ks*6 + g*2 + p
                int ks = blk / 6, r6 = blk % 6;
                int g = r6 >> 1, p = r6 & 1;
                int jb2 = y * 2 + p;
                cpasync16(bbase + (uint32_t)(blk * 512 + q * 16),
                          Wp + ((((c * 2 + ks) * 3 + g) * 32 + jb2) * 32 + q) * 4);
            }
        }
        asm volatile("cp.async.commit_group;" ::: "memory");
    };
#pragma unroll
    for (int c = 0; c < 5; ++c) load_B(c);
    cudaTriggerProgrammaticLaunchCompletion();
    cudaGridDependencySynchronize();

    // ---- post-sync: everything touching the previous step's outputs ----
    const __half* Aimg;       // also the hprev source (fp16 recurrent state)
    const float* b4p = nullptr;
    __half* himg = nullptr;
    if constexpr (MODE == 0) {
        Aimg = g_h0seq[zt];
        himg = g_h0seq[zt + 1];
        b4p = g_b4[0];
    } else if constexpr (MODE == 2) {
        Aimg = (zt == 0) ? g_h1h[0] : g_hdh[zt & 1];
        himg = g_hdh[(zt + 1) & 1];
        b4p = g_b4[2];
    } else if constexpr (MODE == 3) {
        Aimg = g_h1h[zt & 1];
        himg = g_h1h[(zt + 1) & 1];
        b4p = g_b4[1];
    } else {
        Aimg = g_h0seq[zt + 1];   // gi(t) = h0(t+1) @ Wih1^T
    }

    float bfc0 = 0.f, bfc1 = 0.f;
    if constexpr (MODE == 2) { bfc0 = bfc[0]; bfc1 = bfc[1]; }

    float acc[3][2][2][4];
#pragma unroll
    for (int s = 0; s < 3; ++s)
#pragma unroll
        for (int mf = 0; mf < 2; ++mf)
#pragma unroll
            for (int nf = 0; nf < 2; ++nf)
#pragma unroll
                for (int q = 0; q < 4; ++q) acc[s][mf][nf][q] = 0.0f;

    const int laneRow = (lane & 7) + ((lane >> 3) & 1) * 8;
    const int laneCol = (lane >> 4) * 8;
    const uint32_t aoff = (uint32_t)(((wm * 32 + laneRow) * 40 + laneCol) * 2);

    auto load_A = [&](int c) {
        const uint32_t abase = sb + (c % NSTAGE) * SMA_BYTES;
#pragma unroll
        for (int i = 0; i < 2; ++i) {
            int u = tid + i * 256;                // 0..511
            int row = u >> 2, c8 = (u & 3) << 3;
            cpasync16(abase + (uint32_t)((row * 40 + c8) * 2),
                      Aimg + (m0 + row) * 512 + c * 32 + c8);
        }
        asm volatile("cp.async.commit_group;" ::: "memory");
    };
    auto load_AB = [&](int c) {
        const int b = c % NSTAGE;
        const uint32_t abase = sb + b * SMA_BYTES;
        const uint32_t bbase = sb + SMB_OFF + b * SMB_BYTES;
#pragma unroll
        for (int i = 0; i < 2; ++i) {
            int u = tid + i * 256;
            int row = u >> 2, c8 = (u & 3) << 3;
            cpasync16(abase + (uint32_t)((row * 40 + c8) * 2),
                      Aimg + (m0 + row) * 512 + c * 32 + c8);
        }
#pragma unroll
        for (int i = 0; i < 2; ++i) {
            int u = tid + i * 256;
            if (u < 384) {
                int blk = u >> 5, q = u & 31;
                int ks = blk / 6, r6 = blk % 6;
                int g = r6 >> 1, p = r6 & 1;
                int jb2 = y * 2 + p;
                cpasync16(bbase + (uint32_t)(blk * 512 + q * 16),
                          Wp + ((((c * 2 + ks) * 3 + g) * 32 + jb2) * 32 + q) * 4);
            }
        }
        asm volatile("cp.async.commit_group;" ::: "memory");
    };

    // prologue A loads for chunks 0..4. Pending group order: B0..B4, A0..A4.
#pragma unroll
    for (int c = 0; c < 5; ++c) load_A(c);

    for (int cg = 0; cg < 16; ++cg) {
        if (cg < 12)
            asm volatile("cp.async.wait_group 4;" ::: "memory");
        else if (cg == 12)
            asm volatile("cp.async.wait_group 3;" ::: "memory");
        else if (cg == 13)
            asm volatile("cp.async.wait_group 2;" ::: "memory");
        else if (cg == 14)
            asm volatile("cp.async.wait_group 1;" ::: "memory");
        else
            asm volatile("cp.async.wait_group 0;" ::: "memory");
        __syncthreads();
        if (cg + 5 < 16) load_AB(cg + 5);
        const int b = cg % NSTAGE;
        const uint32_t abase = sb + b * SMA_BYTES;
        const uint4* sB = reinterpret_cast<const uint4*>(smem + SMB_OFF + b * SMB_BYTES);
#pragma unroll
        for (int ks = 0; ks < 2; ++ks) {   // 2 x k16 per 32-col chunk
            uint32_t a[2][4];
            ldsm4(a[0], abase + aoff + ks * 32);
            ldsm4(a[1], abase + aoff + 1280 + ks * 32);   // mf=1: +16 rows * 80B
#pragma unroll
            for (int g = 0; g < 3; ++g) {
                const uint4 bv = sB[((ks * 3 + g) * 2 + wn) * 32 + lane];
                mma16(acc[g][0][0], a[0][0], a[0][1], a[0][2], a[0][3], bv.x, bv.y);
                mma16(acc[g][1][0], a[1][0], a[1][1], a[1][2], a[1][3], bv.x, bv.y);
                mma16(acc[g][0][1], a[0][0], a[0][1], a[0][2], a[0][3], bv.z, bv.w);
                mma16(acc[g][1][1], a[1][0], a[1][1], a[1][2], a[1][3], bv.z, bv.w);
            }
        }
    }

    // ------------- epilogue -------------
    if constexpr (MODE == 4) {
#pragma unroll
        for (int mf = 0; mf < 2; ++mf) {
#pragma unroll
            for (int rr = 0; rr < 2; ++rr) {
                int m = m0 + wm * 32 + mf * 16 + rr * 8 + (lane >> 2);
                size_t base = ((size_t)zt * B_ + m) * 1536;
#pragma unroll
                for (int nf = 0; nf < 2; ++nf) {
                    int j = n0 + wn * 16 + nf * 8 + (lane & 3) * 2;
#pragma unroll
                    for (int g = 0; g < 3; ++g) {
                        __half2 hv = __floats2half2_rn(acc[g][mf][nf][rr * 2],
                                                       acc[g][mf][nf][rr * 2 + 1]);
                        *reinterpret_cast<__half2*>(&g_gi[base + g * 512 + j]) = hv;
                    }
                }
            }
        }
        return;
    }

#pragma unroll
    for (int mf = 0; mf < 2; ++mf) {
#pragma unroll
        for (int rr = 0; rr < 2; ++rr) {
            int m = m0 + wm * 32 + mf * 16 + rr * 8 + (lane >> 2);
            float4 xr = make_float4(0.f, 0.f, 0.f, 0.f);
            float2 x2 = make_float2(0.f, 0.f);
            if constexpr (MODE == 0) xr = *reinterpret_cast<const float4*>(&x[m * 120 + zt * 4]);
            if constexpr (MODE == 2) {
                if (zt == 0) {
                    x2 = *reinterpret_cast<const float2*>(&g_decin0[m * 2]);
                } else {
                    float2 p = *reinterpret_cast<const float2*>(&g_pred[(zt - 1) % 3][m * 2]);
                    x2 = make_float2(p.x + bfc0, p.y + bfc1);
                    if (y == 0 && wn == 0 && (lane & 3) == 0) {
                        out[m * 120 + (zt - 1) * 2] = x2.x;
                        out[m * 120 + (zt - 1) * 2 + 1] = x2.y;
                    }
                }
            }
            size_t gibase = 0;
            if constexpr (MODE == 3) gibase = ((size_t)zt * B_ + m) * 1536;
            float pp0 = 0.f, pp1 = 0.f;
#pragma unroll
            for (int nf = 0; nf < 2; ++nf) {
                int j = n0 + wn * 16 + nf * 8 + (lane & 3) * 2;
                // hprev from the fp16 recurrent image (same buffer as MMA A operand)
                float2 ho = __half22float2(
                    *reinterpret_cast<const __half2*>(&Aimg[m * 512 + j]));
                float2 gr2 = make_float2(0.f, 0.f), gz2 = gr2, gn2 = gr2;
                if constexpr (MODE == 3) {
                    gr2 = __half22float2(*reinterpret_cast<const __half2*>(&g_gi[gibase + j]));
                    gz2 = __half22float2(
                        *reinterpret_cast<const __half2*>(&g_gi[gibase + 512 + j]));
                    gn2 = __half22float2(
                        *reinterpret_cast<const __half2*>(&g_gi[gibase + 1024 + j]));
                }
                float hnew[2];
#pragma unroll
                for (int cc = 0; cc < 2; ++cc) {
                    int jj = j + cc;
                    float4 bb = *reinterpret_cast<const float4*>(&b4p[jj * 4]);
                    int q = rr * 2 + cc;
                    float gir = 0.f, giz = 0.f, gin = 0.f;
                    if constexpr (MODE == 0) {
                        float4 wr = *reinterpret_cast<const float4*>(&Wraw[jj * 4]);
                        float4 wz = *reinterpret_cast<const float4*>(&Wraw[(jj + 512) * 4]);
                        float4 wn4 = *reinterpret_cast<const float4*>(&Wraw[(jj + 1024) * 4]);
                        gir = xr.x * wr.x + xr.y * wr.y + xr.z * wr.z + xr.w * wr.w;
                        giz = xr.x * wz.x + xr.y * wz.y + xr.z * wz.z + xr.w * wz.w;
                        gin = xr.x * wn4.x + xr.y * wn4.y + xr.z * wn4.z + xr.w * wn4.w;
                    } else if constexpr (MODE == 2) {
                        float2 wr = *reinterpret_cast<const float2*>(&Wraw[jj * 2]);
                        float2 wz = *reinterpret_cast<const float2*>(&Wraw[(jj + 512) * 2]);
                        float2 wn2 = *reinterpret_cast<const float2*>(&Wraw[(jj + 1024) * 2]);
                        gir = x2.x * wr.x + x2.y * wr.y;
                        giz = x2.x * wz.x + x2.y * wz.y;
                        gin = x2.x * wn2.x + x2.y * wn2.y;
                    } else {
                        gir = cc ? gr2.y : gr2.x;
                        giz = cc ? gz2.y : gz2.x;
                        gin = cc ? gn2.y : gn2.x;
                    }
                    float rg = sigf(acc[0][mf][nf][q] + gir + bb.x);
                    float zg = sigf(acc[1][mf][nf][q] + giz + bb.y);
                    float ng = tanhf(gin + bb.z + rg * (acc[2][mf][nf][q] + bb.w));
                    float hprev = cc ? ho.y : ho.x;
                    hnew[cc] = (1.0f - zg) * ng + zg * hprev;
                    if constexpr (MODE == 2) {
                        pp0 += hnew[cc] * Wfc[jj];
                        pp1 += hnew[cc] * Wfc[512 + jj];
                    }
                }
                __half2 hh = __floats2half2_rn(hnew[0], hnew[1]);
                *reinterpret_cast<__half2*>(&himg[m * 512 + j]) = hh;
            }
            if constexpr (MODE == 2) {
                atomicAdd(&g_pred[zt % 3][m * 2], pp0);
                atomicAdd(&g_pred[zt % 3][m * 2 + 1], pp1);
            }
        }
    }

    if constexpr (MODE == 2) {   // zero the phase step t+1 will accumulate into
        if (y == 1) {
            g_pred[(zt + 1) % 3][blockIdx.x * 256 + tid] = 0.0f;
        }
    }
}

// final pred -> out[TPRED-1]
__global__ void fc_final(const float* __restrict__ bfc, float* __restrict__ out) {
    int i = blockIdx.x * blockDim.x + threadIdx.x;
    if (i < B_) {
        float2 p = *reinterpret_cast<const float2*>(&g_pred[(TPRED - 1) % 3][i * 2]);
        out[i * 120 + (TPRED - 1) * 2] = p.x + bfc[0];
        out[i * 120 + (TPRED - 1) * 2 + 1] = p.y + bfc[1];
    }
}

// ------------------ launch ------------------
template <int MODE>
static void launch_step(dim3 grid, bool pdl, int t, const float* x, const float* Wraw,
                        const float* Wfc, const float* bfc, float* out) {
    cudaLaunchConfig_t cfg = {};
    cfg.gridDim = grid;
    cfg.blockDim = dim3(256, 1, 1);
    cfg.dynamicSmemBytes = SMEM_BYTES;
    cfg.stream = 0;
    cudaLaunchAttribute attr[1];
    attr[0].id = cudaLaunchAttributeProgrammaticStreamSerialization;
    attr[0].val.programmaticStreamSerializationAllowed = 1;
    if (pdl) { cfg.attrs = attr; cfg.numAttrs = 1; }
    cudaLaunchKernelEx(&cfg, gru_core<MODE>, t, x, Wraw, Wfc, bfc, out);
}

extern "C" void kernel_launch(void* const* d_in, const int* in_sizes, int n_in,
                              void* d_out, int out_size) {
    (void)in_sizes; (void)n_in; (void)out_size;
    const float* x    = (const float*)d_in[0];
    const float* Wih0 = (const float*)d_in[1];
    const float* Whh0 = (const float*)d_in[2];
    const float* bih0 = (const float*)d_in[3];
    const float* bhh0 = (const float*)d_in[4];
    const float* Wih1 = (const float*)d_in[5];
    const float* Whh1 = (const float*)d_in[6];
    const float* bih1 = (const float*)d_in[7];
    const float* bhh1 = (const float*)d_in[8];
    const float* Wihd = (const float*)d_in[9];
    const float* Whhd = (const float*)d_in[10];
    const float* bihd = (const float*)d_in[11];
    const float* bhhd = (const float*)d_in[12];
    const float* Wfc  = (const float*)d_in[13];
    const float* bfc  = (const float*)d_in[14];
    float* out = (float*)d_out;

    cudaFuncSetAttribute(gru_core<0>, cudaFuncAttributeMaxDynamicSharedMemorySize, SMEM_BYTES);
    cudaFuncSetAttribute(gru_core<2>, cudaFuncAttributeMaxDynamicSharedMemorySize, SMEM_BYTES);
    cudaFuncSetAttribute(gru_core<3>, cudaFuncAttributeMaxDynamicSharedMemorySize, SMEM_BYTES);
    cudaFuncSetAttribute(gru_core<4>, cudaFuncAttributeMaxDynamicSharedMemorySize, SMEM_BYTES);

    prep_kernel<<<1024, 256>>>(Whh0, Wih1, Whh1, Whhd,
                               bih0, bhh0, bih1, bhh1, bihd, bhhd);
    init_kernel<<<2048, 256>>>(x);

    dim3 grid(32, 16);
    // encoder layer 0 (sequential). t=0 non-PDL: its weight prefetch reads g_Wp from prep.
    for (int t = 0; t < TOBS; ++t) {
        launch_step<0>(grid, t > 0, t, x, Wih0, nullptr, nullptr, nullptr);
    }
    // batched layer-1 input GEMM for all timesteps (fully parallel)
    launch_step<4>(dim3(32, 16, TOBS), true, 0, x, nullptr, nullptr, nullptr, nullptr);
    // encoder layer 1 (sequential, gh-only)
    for (int t = 0; t < TOBS; ++t) {
        launch_step<3>(grid, true, t, x, nullptr, nullptr, nullptr, nullptr);
    }
    // decoder (FC fused)
    for (int td = 0; td < TPRED; ++td) {
        launch_step<2>(grid, true, td, x, Wihd, Wfc, bfc, out);
    }
    fc_final<<<16, 256>>>(bfc, out);
}